// round 14
// baseline (speedup 1.0000x reference)
#include <cuda_runtime.h>
#include <cuda_bf16.h>
#include <math.h>

#define VV   50000
#define VB   64
#define VS   512
#define VE   256
#define VH   512
#define VT   64
#define G3H  1536

typedef unsigned long long ull;

// ---------------------------------------------------------------------------
// Scratch (device globals; runtime allocation is forbidden)
// ---------------------------------------------------------------------------
// states slot 0 = h0(zeros); slot s+1 = h after step s.
// Layout per slot: [c=k/4][b][k%4]  (chunk-interleaved)
__device__ float g_states[(size_t)(VS + 1) * VB * VH];
__device__ int g_tok[VB * VS];                            // int32 tokens [b][s]
__device__ unsigned g_bar_count;

// ---------------------------------------------------------------------------
// f32x2 helpers
// ---------------------------------------------------------------------------
__device__ __forceinline__ ull fma2(ull a, ull b, ull c) {
    ull d;
    asm("fma.rn.f32x2 %0, %1, %2, %3;" : "=l"(d) : "l"(a), "l"(b), "l"(c));
    return d;
}
__device__ __forceinline__ ull pack2(float x, float y) {
    ull d;
    asm("mov.b64 %0, {%1, %2};" : "=l"(d) : "f"(x), "f"(y));
    return d;
}
__device__ __forceinline__ void unpk(ull a, float& x, float& y) {
    asm("mov.b64 {%0, %1}, %2;" : "=f"(x), "=f"(y) : "l"(a));
}
__device__ __forceinline__ float sum2(ull a) {
    float x, y; unpk(a, x, y); return x + y;
}
__device__ __forceinline__ ulonglong2 ldcg128v(const void* p) {
    ulonglong2 r;
    asm volatile("ld.global.cg.v2.u64 {%0, %1}, [%2];"
                 : "=l"(r.x), "=l"(r.y) : "l"(p));
    return r;
}
__device__ __forceinline__ ulonglong2 ldnc128v(const void* p) {
    ulonglong2 r;
    asm("ld.global.nc.v2.u64 {%0, %1}, [%2];"
        : "=l"(r.x), "=l"(r.y) : "l"(p));
    return r;
}

// ---------------------------------------------------------------------------
// Token prologue: detect int32 vs int64 on device, convert+clamp into g_tok.
// ---------------------------------------------------------------------------
__global__ void tok_kernel(const int* __restrict__ raw) {
    __shared__ int is64;
    const int tid = threadIdx.x;
    if (tid == 0) {
        int z = 1;
        for (int i = 0; i < 32; i++)
            if (raw[2 * i + 1] != 0) { z = 0; break; }
        is64 = z;
    }
    __syncthreads();
    const int stride = is64 ? 2 : 1;
    for (int i = tid; i < VB * VS; i += 256) {
        int t = raw[(size_t)i * stride];
        t = (t < 0) ? 0 : ((t >= VV) ? (VV - 1) : t);
        g_tok[i] = t;
    }
}

// ---------------------------------------------------------------------------
// Init: zero d_out, zero h0 slot, reset barrier counter (runs every replay)
// ---------------------------------------------------------------------------
__global__ void init_kernel(float* out, int out_size) {
    int i = blockIdx.x * blockDim.x + threadIdx.x;
    int stride = gridDim.x * blockDim.x;
    for (int j = i; j < out_size; j += stride) out[j] = 0.0f;
    for (int j = i; j < VB * VH; j += stride) g_states[j] = 0.0f;
    if (i == 0) g_bar_count = 0u;
}

// ---------------------------------------------------------------------------
// Kernel B: persistent fused GRU. 128 CTAs x 512 threads.
// thread = (ul:4, bq:16, ks:8). h-dot path = R8-proven direct-LDG ring.
// NEW: gi (x_t @ W_ih^T + b_ih) for step s+1 is computed in-kernel per CTA
// (its own 12 columns only) during the barrier-slack window, with W_ih slice
// pinned in SMEM and gi carried in registers. gi_kernel + g_gi eliminated.
// ---------------------------------------------------------------------------
#define GRU_CTAS 128
#define WPITCH   516
#define WIHP     260
// dynamic smem layout (floats)
#define WS_OFF   0
#define WIH_OFF  (WS_OFF + 12 * WPITCH)          // 6192
#define PART_OFF (WIH_OFF + 12 * WIHP)           // 9312
#define GIP_OFF  (PART_OFF + 24 * 256)           // 15456
#define TOK_OFF  (GIP_OFF + 24 * 256)            // 21600
#define GRU_SMEM_B ((TOK_OFF + 64) * 4)          // 86656 bytes

__global__ void __launch_bounds__(512, 1) gru_kernel(const float* __restrict__ Whh,
                                                     const float* __restrict__ bhh,
                                                     const float* __restrict__ Wih,
                                                     const float* __restrict__ bih,
                                                     const float* __restrict__ emb) {
    extern __shared__ __align__(16) float dyn[];
    float* ws   = dyn + WS_OFF;
    float* wihs = dyn + WIH_OFF;
    float* part = dyn + PART_OFF;
    float* gip  = dyn + GIP_OFF;
    int*   tokm = (int*)(dyn + TOK_OFF);

    const int tid = threadIdx.x;
    const int cta = blockIdx.x;
    const int ul = tid & 3;                   // unit (0..3)
    const int bq = (tid >> 2) & 15;           // base batch row (0..15)
    const int ks = tid >> 6;                  // k-eighth (0..7)
    const int u  = cta * 4 + ul;

    // W_hh slice -> SMEM (rows g*4+uu, pitch 516)
    for (int idx = tid; idx < 12 * VH; idx += 512) {
        const int lr = idx >> 9, k = idx & 511;
        const int g = lr >> 2, uu = lr & 3;
        ws[lr * WPITCH + k] = Whh[(size_t)(g * VH + cta * 4 + uu) * VH + k];
    }
    // W_ih slice -> SMEM (rows g*4+uu, pitch 260)
    for (int idx = tid; idx < 12 * VE; idx += 512) {
        const int lr = idx >> 8, k = idx & 255;
        const int g = lr >> 2, uu = lr & 3;
        wihs[lr * WIHP + k] = Wih[(size_t)(g * VH + cta * 4 + uu) * VE + k];
    }
    const float bR = bhh[u], bZ = bhh[VH + u], bN = bhh[2 * VH + u];
    const float biR = bih[u], biZ = bih[VH + u], biN = bih[2 * VH + u];
    __syncthreads();

    // weight chunk pointers (h-dot), pre-offset to this thread's eighth
    const ulonglong2* wR = (const ulonglong2*)&ws[(0 + ul) * WPITCH] + ks * 16;
    const ulonglong2* wZ = (const ulonglong2*)&ws[(4 + ul) * WPITCH] + ks * 16;
    const ulonglong2* wN = (const ulonglong2*)&ws[(8 + ul) * WPITCH] + ks * 16;
    // W_ih chunk pointers (gi), this thread's 32-k slice
    const ulonglong2* iR = (const ulonglong2*)&wihs[(0 + ul) * WIHP + ks * 32];
    const ulonglong2* iZ = (const ulonglong2*)&wihs[(4 + ul) * WIHP + ks * 32];
    const ulonglong2* iN = (const ulonglong2*)&wihs[(8 + ul) * WIHP + ks * 32];

    // 4-slot ring of h chunk data (4 batch rows per chunk)
    ulonglong2 hA[4], hB[4], hC[4], hD[4];

#define PRE(c, sl)                                                          \
    {                                                                       \
        const char* p = hb8 + (c) * 1024 + bq * 16;                         \
        hA[sl] = ldcg128v(p);                                               \
        hB[sl] = ldcg128v(p + 256);                                         \
        hC[sl] = ldcg128v(p + 512);                                         \
        hD[sl] = ldcg128v(p + 768);                                         \
    }

#define COMP(c, sl)                                                         \
    {                                                                       \
        const ulonglong2 r2 = wR[(c)];                                      \
        const ulonglong2 z2 = wZ[(c)];                                      \
        const ulonglong2 n2 = wN[(c)];                                      \
        aR0 = fma2(hA[sl].x, r2.x, aR0); aR0 = fma2(hA[sl].y, r2.y, aR0);   \
        aR1 = fma2(hB[sl].x, r2.x, aR1); aR1 = fma2(hB[sl].y, r2.y, aR1);   \
        aR2 = fma2(hC[sl].x, r2.x, aR2); aR2 = fma2(hC[sl].y, r2.y, aR2);   \
        aR3 = fma2(hD[sl].x, r2.x, aR3); aR3 = fma2(hD[sl].y, r2.y, aR3);   \
        aZ0 = fma2(hA[sl].x, z2.x, aZ0); aZ0 = fma2(hA[sl].y, z2.y, aZ0);   \
        aZ1 = fma2(hB[sl].x, z2.x, aZ1); aZ1 = fma2(hB[sl].y, z2.y, aZ1);   \
        aZ2 = fma2(hC[sl].x, z2.x, aZ2); aZ2 = fma2(hC[sl].y, z2.y, aZ2);   \
        aZ3 = fma2(hD[sl].x, z2.x, aZ3); aZ3 = fma2(hD[sl].y, z2.y, aZ3);   \
        aN0 = fma2(hA[sl].x, n2.x, aN0); aN0 = fma2(hA[sl].y, n2.y, aN0);   \
        aN1 = fma2(hB[sl].x, n2.x, aN1); aN1 = fma2(hB[sl].y, n2.y, aN1);   \
        aN2 = fma2(hC[sl].x, n2.x, aN2); aN2 = fma2(hC[sl].y, n2.y, aN2);   \
        aN3 = fma2(hD[sl].x, n2.x, aN3); aN3 = fma2(hD[sl].y, n2.y, aN3);   \
    }

// gi slice for the CTA's 12 columns: partials over this thread's 32 k,
// 4 batch rows (bq+16j). Stores 12 partials to gip[] (same layout as part[]).
#define GI_BLOCK                                                            \
    {                                                                       \
        const int t0 = tokm[bq];                                            \
        const int t1 = tokm[bq + 16];                                       \
        const int t2 = tokm[bq + 32];                                       \
        const int t3 = tokm[bq + 48];                                       \
        const char* e0 = (const char*)emb + ((size_t)t0 << 10) + ks * 128;  \
        const char* e1 = (const char*)emb + ((size_t)t1 << 10) + ks * 128;  \
        const char* e2 = (const char*)emb + ((size_t)t2 << 10) + ks * 128;  \
        const char* e3 = (const char*)emb + ((size_t)t3 << 10) + ks * 128;  \
        ull gR0 = 0, gR1 = 0, gR2 = 0, gR3 = 0;                             \
        ull gZ0 = 0, gZ1 = 0, gZ2 = 0, gZ3 = 0;                             \
        ull gN0 = 0, gN1 = 0, gN2 = 0, gN3 = 0;                             \
        _Pragma("unroll")                                                   \
        for (int c8 = 0; c8 < 8; c8++) {                                    \
            const ulonglong2 w_r = iR[c8];                                  \
            const ulonglong2 w_z = iZ[c8];                                  \
            const ulonglong2 w_n = iN[c8];                                  \
            const ulonglong2 a0 = ldnc128v(e0 + c8 * 16);                   \
            const ulonglong2 a1 = ldnc128v(e1 + c8 * 16);                   \
            const ulonglong2 a2 = ldnc128v(e2 + c8 * 16);                   \
            const ulonglong2 a3 = ldnc128v(e3 + c8 * 16);                   \
            gR0 = fma2(a0.x, w_r.x, gR0); gR0 = fma2(a0.y, w_r.y, gR0);     \
            gR1 = fma2(a1.x, w_r.x, gR1); gR1 = fma2(a1.y, w_r.y, gR1);     \
            gR2 = fma2(a2.x, w_r.x, gR2); gR2 = fma2(a2.y, w_r.y, gR2);     \
            gR3 = fma2(a3.x, w_r.x, gR3); gR3 = fma2(a3.y, w_r.y, gR3);     \
            gZ0 = fma2(a0.x, w_z.x, gZ0); gZ0 = fma2(a0.y, w_z.y, gZ0);     \
            gZ1 = fma2(a1.x, w_z.x, gZ1); gZ1 = fma2(a1.y, w_z.y, gZ1);     \
            gZ2 = fma2(a2.x, w_z.x, gZ2); gZ2 = fma2(a2.y, w_z.y, gZ2);     \
            gZ3 = fma2(a3.x, w_z.x, gZ3); gZ3 = fma2(a3.y, w_z.y, gZ3);     \
            gN0 = fma2(a0.x, w_n.x, gN0); gN0 = fma2(a0.y, w_n.y, gN0);     \
            gN1 = fma2(a1.x, w_n.x, gN1); gN1 = fma2(a1.y, w_n.y, gN1);     \
            gN2 = fma2(a2.x, w_n.x, gN2); gN2 = fma2(a2.y, w_n.y, gN2);     \
            gN3 = fma2(a3.x, w_n.x, gN3); gN3 = fma2(a3.y, w_n.y, gN3);     \
        }                                                                   \
        float* qR = gip + (0 * 8 + ks) * 256 + bq * 4 + ul;                 \
        float* qZ = gip + (1 * 8 + ks) * 256 + bq * 4 + ul;                 \
        float* qN = gip + (2 * 8 + ks) * 256 + bq * 4 + ul;                 \
        qR[0] = sum2(gR0); qR[64] = sum2(gR1); qR[128] = sum2(gR2); qR[192] = sum2(gR3); \
        qZ[0] = sum2(gZ0); qZ[64] = sum2(gZ1); qZ[128] = sum2(gZ2); qZ[192] = sum2(gZ3); \
        qN[0] = sum2(gN0); qN[64] = sum2(gN1); qN[128] = sum2(gN2); qN[192] = sum2(gN3); \
    }

    // carried state (tid<256): gi for current step, previous h value
    float gr = 0.0f, gz = 0.0f, gn = 0.0f, hp = 0.0f;

    // ---- prologue: gi[0] ----
    if (tid < 64) tokm[tid] = g_tok[tid * VS];
    __syncthreads();
    GI_BLOCK
    __syncthreads();
    if (tid < 256) {
        gr = biR; gz = biZ; gn = biN;
#pragma unroll
        for (int k8 = 0; k8 < 8; k8++) {
            gr += gip[(0 * 8 + k8) * 256 + tid];
            gz += gip[(1 * 8 + k8) * 256 + tid];
            gn += gip[(2 * 8 + k8) * 256 + tid];
        }
    }
    __syncthreads();

    for (int s = 0; s < VS; s++) {
        // stage tokens for step s+1 (consumed by GI_BLOCK later this step)
        if (s + 1 < VS && tid < 64) tokm[tid] = g_tok[tid * VS + s + 1];

        const float* hf = g_states + (size_t)s * (VB * VH);
        const char* hb8 = (const char*)hf + ks * 16 * 1024;   // this eighth

        // prime the ring (16 independent 16B LDGs in flight)
        PRE(0, 0); PRE(1, 1); PRE(2, 2); PRE(3, 3);

        ull aR0 = 0, aR1 = 0, aR2 = 0, aR3 = 0;
        ull aZ0 = 0, aZ1 = 0, aZ2 = 0, aZ3 = 0;
        ull aN0 = 0, aN1 = 0, aN2 = 0, aN3 = 0;

#pragma unroll
        for (int c = 0; c < 16; c++) {
            COMP(c, c & 3);
            if (c < 12) PRE(c + 4, c & 3);
        }

        // store h-dot partials: part[(g*8+ks)*256 + b*4 + ul]
        {
            float* pR = part + (0 * 8 + ks) * 256 + bq * 4 + ul;
            float* pZ = part + (1 * 8 + ks) * 256 + bq * 4 + ul;
            float* pN = part + (2 * 8 + ks) * 256 + bq * 4 + ul;
            pR[0] = sum2(aR0); pR[64] = sum2(aR1); pR[128] = sum2(aR2); pR[192] = sum2(aR3);
            pZ[0] = sum2(aZ0); pZ[64] = sum2(aZ1); pZ[128] = sum2(aZ2); pZ[192] = sum2(aZ3);
            pN[0] = sum2(aN0); pN[64] = sum2(aN1); pN[128] = sum2(aN2); pN[192] = sum2(aN3);
        }
        __syncthreads();

        // cross-ks reduction + epilogue (tid<256 -> (b, ul))
        if (tid < 256) {
            float dr = 0.0f, dz = 0.0f, dn = 0.0f;
#pragma unroll
            for (int k8 = 0; k8 < 8; k8++) {
                dr += part[(0 * 8 + k8) * 256 + tid];
                dz += part[(1 * 8 + k8) * 256 + tid];
                dn += part[(2 * 8 + k8) * 256 + tid];
            }
            const float r = __fdividef(1.0f, 1.0f + __expf(-(gr + dr + bR)));
            const float z = __fdividef(1.0f, 1.0f + __expf(-(gz + dz + bZ)));
            const float xn = gn + r * (dn + bN);
            const float n = 1.0f - __fdividef(2.0f, __expf(2.0f * xn) + 1.0f);
            const float hnew = (1.0f - z) * n + z * hp;
            __stcg(g_states + (size_t)(s + 1) * (VB * VH) + cta * 256 + tid, hnew);
            hp = hnew;
        }
        __syncthreads();

        // publish ASAP so other CTAs can proceed
        if (tid == 0) {
            asm volatile("red.release.gpu.global.add.u32 [%0], %1;"
                         :: "l"(&g_bar_count), "r"(1u) : "memory");
        }

        // gi for step s+1 in the barrier-slack window
        if (s + 1 < VS) { GI_BLOCK }
        __syncthreads();
        if (s + 1 < VS && tid < 256) {
            gr = biR; gz = biZ; gn = biN;
#pragma unroll
            for (int k8 = 0; k8 < 8; k8++) {
                gr += gip[(0 * 8 + k8) * 256 + tid];
                gz += gip[(1 * 8 + k8) * 256 + tid];
                gn += gip[(2 * 8 + k8) * 256 + tid];
            }
        }

        // wait for all CTAs to finish step s
        if (tid == 0) {
            const unsigned target = (unsigned)(s + 1) * GRU_CTAS;
            unsigned v;
            do {
                asm volatile("ld.acquire.gpu.global.u32 %0, [%1];"
                             : "=r"(v) : "l"(&g_bar_count) : "memory");
            } while (v < target);
        }
        __syncthreads();
    }
#undef PRE
#undef COMP
#undef GI_BLOCK
}

// ---------------------------------------------------------------------------
// Kernel C: tag_logits = states @ W_tag^T + b_tag ; preds (proven)
// ---------------------------------------------------------------------------
#define WT_PITCH 68

__global__ void __launch_bounds__(256) tag_kernel(const float* __restrict__ Wtag,
                                                  const float* __restrict__ btag,
                                                  float* __restrict__ out,
                                                  int preds_off, int write_preds) {
    __shared__ __align__(16) float Wt[128 * WT_PITCH];

    const int tid = threadIdx.x;
    const int r = tid >> 2;
    const int tg4 = tid & 3;
    const int m = blockIdx.x * 64 + r;        // m = b*512 + s
    const int bb = m >> 9, s = m & 511;
    const float* st = g_states + (size_t)(s + 1) * (VB * VH) + bb * 4;

    float acc[16];
#pragma unroll
    for (int j = 0; j < 16; j++) acc[j] = btag[tg4 * 16 + j];

    for (int cc = 0; cc < 4; cc++) {
        __syncthreads();
        for (int idx = tid; idx < VT * 128; idx += 256) {
            const int tg = idx >> 7, kk = idx & 127;
            Wt[kk * WT_PITCH + tg] = Wtag[(size_t)tg * VH + cc * 128 + kk];
        }
        __syncthreads();
#pragma unroll 4
        for (int c = 0; c < 32; c++) {
            const float4 a4 = __ldg((const float4*)(st + (size_t)(cc * 32 + c) * 256));
#pragma unroll
            for (int kq = 0; kq < 4; kq++) {
                const float av = (kq == 0) ? a4.x : (kq == 1) ? a4.y : (kq == 2) ? a4.z : a4.w;
                const float4* w4p = (const float4*)&Wt[(c * 4 + kq) * WT_PITCH + tg4 * 16];
                const float4 w0 = w4p[0], w1 = w4p[1], w2 = w4p[2], w3 = w4p[3];
                acc[0]  = fmaf(av, w0.x, acc[0]);  acc[1]  = fmaf(av, w0.y, acc[1]);
                acc[2]  = fmaf(av, w0.z, acc[2]);  acc[3]  = fmaf(av, w0.w, acc[3]);
                acc[4]  = fmaf(av, w1.x, acc[4]);  acc[5]  = fmaf(av, w1.y, acc[5]);
                acc[6]  = fmaf(av, w1.z, acc[6]);  acc[7]  = fmaf(av, w1.w, acc[7]);
                acc[8]  = fmaf(av, w2.x, acc[8]);  acc[9]  = fmaf(av, w2.y, acc[9]);
                acc[10] = fmaf(av, w2.z, acc[10]); acc[11] = fmaf(av, w2.w, acc[11]);
                acc[12] = fmaf(av, w3.x, acc[12]); acc[13] = fmaf(av, w3.y, acc[13]);
                acc[14] = fmaf(av, w3.z, acc[14]); acc[15] = fmaf(av, w3.w, acc[15]);
            }
        }
    }

    {
        float* dst = out + (size_t)m * VT + tg4 * 16;
#pragma unroll
        for (int q = 0; q < 4; q++) {
            float4 v;
            v.x = acc[q * 4]; v.y = acc[q * 4 + 1];
            v.z = acc[q * 4 + 2]; v.w = acc[q * 4 + 3];
            *(float4*)(dst + q * 4) = v;
        }
    }

    if (write_preds) {
        float v = acc[0]; int bi = 0;
#pragma unroll
        for (int j = 1; j < 16; j++) { if (acc[j] > v) { v = acc[j]; bi = j; } }
        bi += tg4 * 16;
#pragma unroll
        for (int off = 2; off >= 1; off >>= 1) {
            const float v2 = __shfl_down_sync(0xFFFFFFFFu, v, off, 4);
            const int i2 = __shfl_down_sync(0xFFFFFFFFu, bi, off, 4);
            if (v2 > v) { v = v2; bi = i2; }
        }
        if (tg4 == 0) {
            const int t = g_tok[bb * VS + s];
            out[preds_off + m] = (t != 0) ? (float)bi : 0.0f;
        }
    }
}

// ---------------------------------------------------------------------------
extern "C" void kernel_launch(void* const* d_in, const int* in_sizes, int n_in,
                              void* d_out, int out_size) {
    const int*   tokens_raw = (const int*)d_in[0];
    const float* emb  = (const float*)d_in[1];
    const float* Wih  = (const float*)d_in[2];
    const float* Whh  = (const float*)d_in[3];
    const float* bih  = (const float*)d_in[4];
    const float* bhh  = (const float*)d_in[5];
    const float* Wtag = (const float*)d_in[6];
    const float* btag = (const float*)d_in[7];
    float* out = (float*)d_out;

    const int logits_n = VB * VS * VT;                 // 2097152
    const int write_preds = (out_size >= logits_n + VB * VS) ? 1 : 0;

    static int smem_set = 0;
    if (!smem_set) {
        cudaFuncSetAttribute(gru_kernel, cudaFuncAttributeMaxDynamicSharedMemorySize, GRU_SMEM_B);
        smem_set = 1;
    }

    tok_kernel<<<1, 256>>>(tokens_raw);
    init_kernel<<<256, 256>>>(out, out_size);
    gru_kernel<<<GRU_CTAS, 512, GRU_SMEM_B>>>(Whh, bhh, Wih, bih, emb);
    tag_kernel<<<512, 256>>>(Wtag, btag, out, logits_n, write_preds);
}

// round 15
// speedup vs baseline: 1.3527x; 1.3527x over previous
#include <cuda_runtime.h>
#include <cuda_bf16.h>
#include <math.h>

#define VV   50000
#define VB   64
#define VS   512
#define VE   256
#define VH   512
#define VT   64
#define G3H  1536

typedef unsigned long long ull;

// ---------------------------------------------------------------------------
// Scratch (device globals; runtime allocation is forbidden)
// ---------------------------------------------------------------------------
__device__ float g_gi[(size_t)VS * VB * G3H];            // [s][b][3H]
// states slot 0 = h0(zeros); slot s+1 = h after step s.
// Layout per slot: [c=k/4][b][k%4]  (chunk-interleaved)
__device__ float g_states[(size_t)(VS + 1) * VB * VH];
__device__ int g_tok[VB * VS];                            // int32 tokens [b][s]
__device__ unsigned g_bar_count;

// ---------------------------------------------------------------------------
// f32x2 helpers
// ---------------------------------------------------------------------------
__device__ __forceinline__ ull fma2(ull a, ull b, ull c) {
    ull d;
    asm("fma.rn.f32x2 %0, %1, %2, %3;" : "=l"(d) : "l"(a), "l"(b), "l"(c));
    return d;
}
__device__ __forceinline__ ull pack2(float x, float y) {
    ull d;
    asm("mov.b64 %0, {%1, %2};" : "=l"(d) : "f"(x), "f"(y));
    return d;
}
__device__ __forceinline__ void unpk(ull a, float& x, float& y) {
    asm("mov.b64 {%0, %1}, %2;" : "=f"(x), "=f"(y) : "l"(a));
}
__device__ __forceinline__ float sum2(ull a) {
    float x, y; unpk(a, x, y); return x + y;
}
__device__ __forceinline__ ulonglong2 ldcg128v(const void* p) {
    ulonglong2 r;
    asm volatile("ld.global.cg.v2.u64 {%0, %1}, [%2];"
                 : "=l"(r.x), "=l"(r.y) : "l"(p));
    return r;
}

// ---------------------------------------------------------------------------
// Token prologue: detect int32 vs int64 on device, convert+clamp into g_tok.
// ---------------------------------------------------------------------------
__global__ void tok_kernel(const int* __restrict__ raw) {
    __shared__ int is64;
    const int tid = threadIdx.x;
    if (tid == 0) {
        int z = 1;
        for (int i = 0; i < 32; i++)
            if (raw[2 * i + 1] != 0) { z = 0; break; }
        is64 = z;
    }
    __syncthreads();
    const int stride = is64 ? 2 : 1;
    for (int i = tid; i < VB * VS; i += 256) {
        int t = raw[(size_t)i * stride];
        t = (t < 0) ? 0 : ((t >= VV) ? (VV - 1) : t);
        g_tok[i] = t;
    }
}

// ---------------------------------------------------------------------------
// Init: zero d_out, zero h0 slot, reset barrier (runs every replay)
// ---------------------------------------------------------------------------
__global__ void init_kernel(float* out, int out_size) {
    int i = blockIdx.x * blockDim.x + threadIdx.x;
    int stride = gridDim.x * blockDim.x;
    for (int j = i; j < out_size; j += stride) out[j] = 0.0f;
    for (int j = i; j < VB * VH; j += stride) g_states[j] = 0.0f;
    if (i == 0) g_bar_count = 0u;
}

// ---------------------------------------------------------------------------
// Kernel A: gi[s][b][:] = emb[tokens[b][s]] @ W_ih^T + b_ih   (proven)
// ---------------------------------------------------------------------------
__global__ void __launch_bounds__(256) gi_kernel(const float* __restrict__ emb,
                                                 const float* __restrict__ Wih,
                                                 const float* __restrict__ bih) {
    __shared__ __align__(16) float As[32 * 64];    // [k][m]
    __shared__ __align__(16) float Bs[32 * 128];   // [k][g]
    __shared__ int tok[64];

    const int tid = threadIdx.x;
    const int s = blockIdx.y;
    const int g0 = blockIdx.x * 128;

    if (tid < 64) tok[tid] = g_tok[tid * VS + s];

    const int rg = tid & 15;
    const int cg = tid >> 4;

    ull acc[4][4];
    {
        const float4 b0 = *(const float4*)&bih[g0 + cg * 8];
        const float4 b1 = *(const float4*)&bih[g0 + cg * 8 + 4];
        ull p0 = pack2(b0.x, b0.y), p1 = pack2(b0.z, b0.w);
        ull p2 = pack2(b1.x, b1.y), p3 = pack2(b1.z, b1.w);
#pragma unroll
        for (int i = 0; i < 4; i++) {
            acc[i][0] = p0; acc[i][1] = p1; acc[i][2] = p2; acc[i][3] = p3;
        }
    }
    __syncthreads();

    for (int kt = 0; kt < VE; kt += 32) {
        {
            const int arow = tid >> 2, kq = tid & 3;
            const float* src = emb + (size_t)tok[arow] * VE + kt + kq * 8;
            const float4 v0 = *(const float4*)(src);
            const float4 v1 = *(const float4*)(src + 4);
            const int kb = kq * 8;
            As[(kb + 0) * 64 + arow] = v0.x; As[(kb + 1) * 64 + arow] = v0.y;
            As[(kb + 2) * 64 + arow] = v0.z; As[(kb + 3) * 64 + arow] = v0.w;
            As[(kb + 4) * 64 + arow] = v1.x; As[(kb + 5) * 64 + arow] = v1.y;
            As[(kb + 6) * 64 + arow] = v1.z; As[(kb + 7) * 64 + arow] = v1.w;
        }
        {
            const int grow = tid >> 1, kh = tid & 1;
            const float* src = Wih + (size_t)(g0 + grow) * VE + kt + kh * 16;
#pragma unroll
            for (int q = 0; q < 4; q++) {
                const float4 v = *(const float4*)(src + q * 4);
                const int kb = kh * 16 + q * 4;
                Bs[(kb + 0) * 128 + grow] = v.x; Bs[(kb + 1) * 128 + grow] = v.y;
                Bs[(kb + 2) * 128 + grow] = v.z; Bs[(kb + 3) * 128 + grow] = v.w;
            }
        }
        __syncthreads();
#pragma unroll
        for (int k = 0; k < 32; k++) {
            const float4 av = *(const float4*)&As[k * 64 + rg * 4];
            const ull pa0 = pack2(av.x, av.x), pa1 = pack2(av.y, av.y);
            const ull pa2 = pack2(av.z, av.z), pa3 = pack2(av.w, av.w);
            const ulonglong2 bA = *(const ulonglong2*)&Bs[k * 128 + cg * 8];
            const ulonglong2 bB = *(const ulonglong2*)&Bs[k * 128 + cg * 8 + 4];
            acc[0][0] = fma2(pa0, bA.x, acc[0][0]); acc[0][1] = fma2(pa0, bA.y, acc[0][1]);
            acc[0][2] = fma2(pa0, bB.x, acc[0][2]); acc[0][3] = fma2(pa0, bB.y, acc[0][3]);
            acc[1][0] = fma2(pa1, bA.x, acc[1][0]); acc[1][1] = fma2(pa1, bA.y, acc[1][1]);
            acc[1][2] = fma2(pa1, bB.x, acc[1][2]); acc[1][3] = fma2(pa1, bB.y, acc[1][3]);
            acc[2][0] = fma2(pa2, bA.x, acc[2][0]); acc[2][1] = fma2(pa2, bA.y, acc[2][1]);
            acc[2][2] = fma2(pa2, bB.x, acc[2][2]); acc[2][3] = fma2(pa2, bB.y, acc[2][3]);
            acc[3][0] = fma2(pa3, bA.x, acc[3][0]); acc[3][1] = fma2(pa3, bA.y, acc[3][1]);
            acc[3][2] = fma2(pa3, bB.x, acc[3][2]); acc[3][3] = fma2(pa3, bB.y, acc[3][3]);
        }
        __syncthreads();
    }

#pragma unroll
    for (int i = 0; i < 4; i++) {
        float o0, o1, o2, o3, o4, o5, o6, o7;
        unpk(acc[i][0], o0, o1); unpk(acc[i][1], o2, o3);
        unpk(acc[i][2], o4, o5); unpk(acc[i][3], o6, o7);
        float* dst = g_gi + (size_t)(s * VB + rg * 4 + i) * G3H + g0 + cg * 8;
        float4 w0; w0.x = o0; w0.y = o1; w0.z = o2; w0.w = o3;
        float4 w1; w1.x = o4; w1.y = o5; w1.z = o6; w1.w = o7;
        *(float4*)(dst) = w0;
        *(float4*)(dst + 4) = w1;
    }
}

// ---------------------------------------------------------------------------
// Kernel B: persistent GRU, 256 threads, transposed mapping.
// warp = ks (k-eighth, 16 chunks); lane = batch row (rows lane, lane+32).
// Each thread computes all 12 (gate,unit) partials for its 2 rows:
//   - h: 2 LDG.128 per chunk, ZERO lane duplication (warp = 512B contiguous)
//   - weights: 12 broadcast LDS.128 per chunk (all lanes same address)
// Partials via 6 STS.128; reduction/epilogue/barrier = R8-proven.
// ---------------------------------------------------------------------------
#define GRU_CTAS 128
#define WPITCH   512      // weight reads are broadcast; no padding needed

__global__ void __launch_bounds__(256, 1) gru_kernel(const float* __restrict__ Whh,
                                                     const float* __restrict__ bhh) {
    __shared__ __align__(16) float ws[12 * WPITCH];     // 24576 B
    __shared__ __align__(16) float part[24 * 256];      // 24576 B

    const int tid = threadIdx.x;
    const int cta = blockIdx.x;
    const int ks = tid >> 5;                  // warp = k-eighth (0..7)
    const int lane = tid & 31;                // batch row (and row+32)
    const int ul = tid & 3;                   // epilogue unit
    const int u  = cta * 4 + ul;              // epilogue global unit

    // W_hh slice -> SMEM rows g*4+uu (pitch 512)
    for (int idx = tid; idx < 12 * VH; idx += 256) {
        const int lr = idx >> 9, k = idx & 511;
        const int g = lr >> 2, uu = lr & 3;
        ws[lr * WPITCH + k] = Whh[(size_t)(g * VH + cta * 4 + uu) * VH + k];
    }
    const float bR = bhh[u], bZ = bhh[VH + u], bN = bhh[2 * VH + u];
    __syncthreads();

    const int ksc = ks * 16;                  // first chunk of this warp

    // 4-slot ring: h for rows lane and lane+32
    ulonglong2 hx[4], hy[4];

#define PRE(c, sl)                                                          \
    {                                                                       \
        const char* p = hb8 + (size_t)(c) * 1024 + lane * 16;               \
        hx[sl] = ldcg128v(p);                                               \
        hy[sl] = ldcg128v(p + 512);                                         \
    }

#define COMP(c, sl)                                                         \
    {                                                                       \
        const float* wc = ws + (ksc + (c)) * 4;                             \
        _Pragma("unroll")                                                   \
        for (int g = 0; g < 3; g++) {                                       \
            _Pragma("unroll")                                               \
            for (int uu = 0; uu < 4; uu++) {                                \
                const ulonglong2 w2 = *(const ulonglong2*)(wc + (g * 4 + uu) * WPITCH); \
                acc[g][0][uu] = fma2(hx[sl].x, w2.x, acc[g][0][uu]);        \
                acc[g][0][uu] = fma2(hx[sl].y, w2.y, acc[g][0][uu]);        \
                acc[g][1][uu] = fma2(hy[sl].x, w2.x, acc[g][1][uu]);        \
                acc[g][1][uu] = fma2(hy[sl].y, w2.y, acc[g][1][uu]);        \
            }                                                               \
        }                                                                   \
    }

    for (int s = 0; s < VS; s++) {
        const float* hf = g_states + (size_t)s * (VB * VH);
        const char* hb8 = (const char*)hf + ks * 16 * 1024;   // this eighth

        // prime the ring (8 independent 16B LDGs in flight per thread)
        PRE(0, 0); PRE(1, 1); PRE(2, 2); PRE(3, 3);

        // early independent loads (epilogue only)
        const float* gis = g_gi + (size_t)(s * VB + (tid >> 2)) * G3H;
        const float gr = __ldg(gis + u);
        const float gz = __ldg(gis + VH + u);
        const float gn = __ldg(gis + 2 * VH + u);
        const float hp = __ldcg(hf + cta * 256 + tid);

        ull acc[3][2][4];
#pragma unroll
        for (int g = 0; g < 3; g++)
#pragma unroll
            for (int j = 0; j < 2; j++)
#pragma unroll
                for (int uu = 0; uu < 4; uu++) acc[g][j][uu] = 0;

#pragma unroll
        for (int c = 0; c < 16; c++) {
            COMP(c, c & 3);
            if (c < 12) PRE(c + 4, c & 3);
        }

        // store partials: part[(g*8+ks)*256 + row*4 .. +3]  (STS.128, no conflicts)
#pragma unroll
        for (int g = 0; g < 3; g++)
#pragma unroll
            for (int j = 0; j < 2; j++) {
                float4 v;
                v.x = sum2(acc[g][j][0]); v.y = sum2(acc[g][j][1]);
                v.z = sum2(acc[g][j][2]); v.w = sum2(acc[g][j][3]);
                *(float4*)&part[(g * 8 + ks) * 256 + (lane + j * 32) * 4] = v;
            }
        __syncthreads();

        // cross-ks reduction + epilogue (all 256 threads -> (b, ul))
        {
            float dr = 0.0f, dz = 0.0f, dn = 0.0f;
#pragma unroll
            for (int k8 = 0; k8 < 8; k8++) {
                dr += part[(0 * 8 + k8) * 256 + tid];
                dz += part[(1 * 8 + k8) * 256 + tid];
                dn += part[(2 * 8 + k8) * 256 + tid];
            }
            const float r = __fdividef(1.0f, 1.0f + __expf(-(gr + dr + bR)));
            const float z = __fdividef(1.0f, 1.0f + __expf(-(gz + dz + bZ)));
            const float xn = gn + r * (dn + bN);
            const float n = 1.0f - __fdividef(2.0f, __expf(2.0f * xn) + 1.0f);
            const float hnew = (1.0f - z) * n + z * hp;
            __stcg(g_states + (size_t)(s + 1) * (VB * VH) + cta * 256 + tid, hnew);
        }

        // lean grid barrier: release-add on monotonic counter, acquire poll
        __syncthreads();
        if (tid == 0) {
            asm volatile("red.release.gpu.global.add.u32 [%0], %1;"
                         :: "l"(&g_bar_count), "r"(1u) : "memory");
            const unsigned target = (unsigned)(s + 1) * GRU_CTAS;
            unsigned v;
            do {
                asm volatile("ld.acquire.gpu.global.u32 %0, [%1];"
                             : "=r"(v) : "l"(&g_bar_count) : "memory");
            } while (v < target);
        }
        __syncthreads();
    }
#undef PRE
#undef COMP
}

// ---------------------------------------------------------------------------
// Kernel C: tag_logits = states @ W_tag^T + b_tag ; preds (proven)
// ---------------------------------------------------------------------------
#define WT_PITCH 68

__global__ void __launch_bounds__(256) tag_kernel(const float* __restrict__ Wtag,
                                                  const float* __restrict__ btag,
                                                  float* __restrict__ out,
                                                  int preds_off, int write_preds) {
    __shared__ __align__(16) float Wt[128 * WT_PITCH];

    const int tid = threadIdx.x;
    const int r = tid >> 2;
    const int tg4 = tid & 3;
    const int m = blockIdx.x * 64 + r;        // m = b*512 + s
    const int bb = m >> 9, s = m & 511;
    const float* st = g_states + (size_t)(s + 1) * (VB * VH) + bb * 4;

    float acc[16];
#pragma unroll
    for (int j = 0; j < 16; j++) acc[j] = btag[tg4 * 16 + j];

    for (int cc = 0; cc < 4; cc++) {
        __syncthreads();
        for (int idx = tid; idx < VT * 128; idx += 256) {
            const int tg = idx >> 7, kk = idx & 127;
            Wt[kk * WT_PITCH + tg] = Wtag[(size_t)tg * VH + cc * 128 + kk];
        }
        __syncthreads();
#pragma unroll 4
        for (int c = 0; c < 32; c++) {
            const float4 a4 = __ldg((const float4*)(st + (size_t)(cc * 32 + c) * 256));
#pragma unroll
            for (int kq = 0; kq < 4; kq++) {
                const float av = (kq == 0) ? a4.x : (kq == 1) ? a4.y : (kq == 2) ? a4.z : a4.w;
                const float4* w4p = (const float4*)&Wt[(c * 4 + kq) * WT_PITCH + tg4 * 16];
                const float4 w0 = w4p[0], w1 = w4p[1], w2 = w4p[2], w3 = w4p[3];
                acc[0]  = fmaf(av, w0.x, acc[0]);  acc[1]  = fmaf(av, w0.y, acc[1]);
                acc[2]  = fmaf(av, w0.z, acc[2]);  acc[3]  = fmaf(av, w0.w, acc[3]);
                acc[4]  = fmaf(av, w1.x, acc[4]);  acc[5]  = fmaf(av, w1.y, acc[5]);
                acc[6]  = fmaf(av, w1.z, acc[6]);  acc[7]  = fmaf(av, w1.w, acc[7]);
                acc[8]  = fmaf(av, w2.x, acc[8]);  acc[9]  = fmaf(av, w2.y, acc[9]);
                acc[10] = fmaf(av, w2.z, acc[10]); acc[11] = fmaf(av, w2.w, acc[11]);
                acc[12] = fmaf(av, w3.x, acc[12]); acc[13] = fmaf(av, w3.y, acc[13]);
                acc[14] = fmaf(av, w3.z, acc[14]); acc[15] = fmaf(av, w3.w, acc[15]);
            }
        }
    }

    {
        float* dst = out + (size_t)m * VT + tg4 * 16;
#pragma unroll
        for (int q = 0; q < 4; q++) {
            float4 v;
            v.x = acc[q * 4]; v.y = acc[q * 4 + 1];
            v.z = acc[q * 4 + 2]; v.w = acc[q * 4 + 3];
            *(float4*)(dst + q * 4) = v;
        }
    }

    if (write_preds) {
        float v = acc[0]; int bi = 0;
#pragma unroll
        for (int j = 1; j < 16; j++) { if (acc[j] > v) { v = acc[j]; bi = j; } }
        bi += tg4 * 16;
#pragma unroll
        for (int off = 2; off >= 1; off >>= 1) {
            const float v2 = __shfl_down_sync(0xFFFFFFFFu, v, off, 4);
            const int i2 = __shfl_down_sync(0xFFFFFFFFu, bi, off, 4);
            if (v2 > v) { v = v2; bi = i2; }
        }
        if (tg4 == 0) {
            const int t = g_tok[bb * VS + s];
            out[preds_off + m] = (t != 0) ? (float)bi : 0.0f;
        }
    }
}

// ---------------------------------------------------------------------------
extern "C" void kernel_launch(void* const* d_in, const int* in_sizes, int n_in,
                              void* d_out, int out_size) {
    const int*   tokens_raw = (const int*)d_in[0];
    const float* emb  = (const float*)d_in[1];
    const float* Wih  = (const float*)d_in[2];
    const float* Whh  = (const float*)d_in[3];
    const float* bih  = (const float*)d_in[4];
    const float* bhh  = (const float*)d_in[5];
    const float* Wtag = (const float*)d_in[6];
    const float* btag = (const float*)d_in[7];
    float* out = (float*)d_out;

    const int logits_n = VB * VS * VT;                 // 2097152
    const int write_preds = (out_size >= logits_n + VB * VS) ? 1 : 0;

    tok_kernel<<<1, 256>>>(tokens_raw);
    init_kernel<<<256, 256>>>(out, out_size);
    gi_kernel<<<dim3(12, 512), 256>>>(emb, Wih, bih);
    gru_kernel<<<GRU_CTAS, 256>>>(Whh, bhh);
    tag_kernel<<<512, 256>>>(Wtag, btag, out, logits_n, write_preds);
}